// round 14
// baseline (speedup 1.0000x reference)
#include <cuda_runtime.h>
#include <cuda_fp16.h>
#include <cstdint>

#define NPTS 65536
#define MPTS 65536
#define KNB  16
#define TILE 128              // columns per CTA tile (8 pts x 16 nbrs)
#define NTILES 8192
#define GRID 296              // 2 CTAs per SM

// ---------------- device scratch ----------------
__device__ __align__(16) unsigned short g_x[(size_t)NPTS * 64];    // fp16 rows 128B
__device__ __align__(16) unsigned short g_w1e[64 * 80];            // W1|pos|bias|pad
__device__ __align__(16) unsigned short g_w2[128 * 64];
__device__ int g_idx_is64;

// ---------------- smem layout (bytes) ----------------
#define SM_W1   0                      // 64 * 176  = 11264
#define SM_W2   11264                  // 128 * 144 = 18432
#define SM_B1A  29696                  // 128 * 176 = 22528
#define SM_B1B  52224                  // 128 * 176 = 22528
#define SM_H    74752                  // 128 * 144 = 18432
#define SM_TOTAL 93184

// ---------------- helpers ----------------
__device__ __forceinline__ uint32_t smem_u32(const void* p) {
    uint32_t a;
    asm("{ .reg .u64 t; cvta.to.shared.u64 t, %1; cvt.u32.u64 %0, t; }" : "=r"(a) : "l"(p));
    return a;
}
__device__ __forceinline__ void ldsm4(uint32_t (&r)[4], uint32_t addr) {
    asm volatile("ldmatrix.sync.aligned.m8n8.x4.shared.b16 {%0,%1,%2,%3}, [%4];"
                 : "=r"(r[0]), "=r"(r[1]), "=r"(r[2]), "=r"(r[3]) : "r"(addr));
}
__device__ __forceinline__ void stsm4t(uint32_t addr, uint32_t r0, uint32_t r1,
                                       uint32_t r2, uint32_t r3) {
    asm volatile("stmatrix.sync.aligned.m8n8.x4.trans.shared.b16 [%0], {%1,%2,%3,%4};"
                 :: "r"(addr), "r"(r0), "r"(r1), "r"(r2), "r"(r3) : "memory");
}
__device__ __forceinline__ void mma_f32(float (&d)[4], const uint32_t (&a)[4],
                                        uint32_t b0, uint32_t b1) {
    asm volatile("mma.sync.aligned.m16n8k16.row.col.f32.f16.f16.f32 "
                 "{%0,%1,%2,%3}, {%4,%5,%6,%7}, {%8,%9}, {%0,%1,%2,%3};"
                 : "+f"(d[0]), "+f"(d[1]), "+f"(d[2]), "+f"(d[3])
                 : "r"(a[0]), "r"(a[1]), "r"(a[2]), "r"(a[3]), "r"(b0), "r"(b1));
}
#define CP16(dst, src) \
    asm volatile("cp.async.cg.shared.global [%0], [%1], 16;" :: "r"(dst), "l"(src))
#define CP_COMMIT()  asm volatile("cp.async.commit_group;" ::: "memory")
#define CP_WAIT0()   asm volatile("cp.async.wait_group 0;" ::: "memory")
#define BARH(id)     asm volatile("bar.sync %0, 128;" :: "r"(id) : "memory")

__device__ __forceinline__ uint32_t packh2(float a, float b) {
    __half2 h = __floats2half2_rn(a, b);
    return *(uint32_t*)&h;
}

// ---------------- prep ----------------
__global__ __launch_bounds__(256) void prep_all_kernel(const float* __restrict__ x,
                                                       const float* __restrict__ W1,
                                                       const float* __restrict__ b1,
                                                       const float* __restrict__ W2,
                                                       const unsigned int* __restrict__ idx32)
{
    __shared__ unsigned short shhi[128 * 72];
    const int p0 = blockIdx.x * 128;
    const int tid = threadIdx.x;

    for (int idx = tid; idx < 128 * 64; idx += 256) {
        int c = idx >> 7, p = idx & 127;
        float v = x[(size_t)c * NPTS + p0 + p];
        shhi[p * 72 + c] = __half_as_ushort(__float2half_rn(v));
    }

    if (blockIdx.x == 0) {
        if (tid == 0) {
            unsigned int orv = 0;
            for (int i = 0; i < 256; i++) orv |= idx32[2 * i + 1];
            g_idx_is64 = (orv == 0u) ? 1 : 0;
        }
        for (int i = tid; i < 64 * 80; i += 256) {
            int o = i / 80, c = i % 80;
            float v = 0.0f;
            if (c < 67)       v = W1[o * 67 + c];
            else if (c == 67) v = b1[o];
            g_w1e[i] = __half_as_ushort(__float2half_rn(v));
        }
        for (int i = tid; i < 128 * 64; i += 256)
            g_w2[i] = __half_as_ushort(__float2half_rn(W2[i]));
    }
    __syncthreads();
    uint4* dh = (uint4*)(g_x + (size_t)p0 * 64);
    for (int i = tid; i < 1024; i += 256) {
        int p = i >> 3, q = i & 7;
        dh[i] = *(const uint4*)&shhi[p * 72 + q * 8];
    }
}

// ---------------- main persistent kernel: 256 thr, 2 CTAs/SM ----------------
extern __shared__ char smc[];

__global__ __launch_bounds__(256, 2)
void pointnet_mma_kernel(const float* __restrict__ pos,
                         const float* __restrict__ sup,
                         const float* __restrict__ b2,
                         const void* __restrict__ indices,
                         float* __restrict__ out)
{
    const uint32_t sb = smem_u32(smc);
    const int tid = threadIdx.x;
    const int w = tid >> 5;
    const int l = tid & 31;
    const int is64 = g_idx_is64;

    // ---- stage weights once ----
    for (int i = tid; i < 640; i += 256) {            // W1e: 64 rows x 10 chunks
        int o = i / 10, c = i % 10;
        *(uint4*)(smc + SM_W1 + o * 176 + c * 16) = *(const uint4*)(g_w1e + o * 80 + c * 8);
    }
    for (int i = tid; i < 1024; i += 256) {           // W2: 128 rows x 8 chunks
        int o = i >> 3, c = i & 7;
        *(uint4*)(smc + SM_W2 + o * 144 + c * 16) = *(const uint4*)(g_w2 + o * 64 + c * 8);
    }
    __syncthreads();

    // ---- loop-invariant constants ----
    const uint32_t arow1 = sb + SM_W1 + (32 * (w & 1) + ((l >> 3) & 1) * 8 + (l & 7)) * 176;
    const uint32_t boff1 = (uint32_t)(32 * (w >> 1) + ((l >> 4) & 1) * 8 + (l & 7)) * 176;
    const uint32_t arow2 = sb + SM_W2 + (32 * (w & 3) + ((l >> 3) & 1) * 8 + (l & 7)) * 144;
    const uint32_t brow2 = sb + SM_H  + (64 * (w >> 2) + ((l >> 4) & 1) * 8 + (l & 7)) * 144;
    const uint32_t hst   = sb + SM_H + (32 * (w >> 1) + 8 * (l >> 3) + (l & 7)) * 144;
    const int hbar = 1 + (w >> 2);                    // named barrier id per H-half

    // output rows owned by this lane (pool epilogue) + their biases
    const int orow0 = 32 * (w & 3) + (l >> 2);        // mb=0, m-half 0 (+8 for half 1)
    const int mcol  = 4 * (w >> 2);                   // 4 consecutive support points
    const float bo00 = __ldg(&b2[orow0]);
    const float bo01 = __ldg(&b2[orow0 + 8]);
    const float bo10 = __ldg(&b2[orow0 + 16]);
    const float bo11 = __ldg(&b2[orow0 + 24]);

    const unsigned gp   = tid >> 1;
    const unsigned half = tid & 1;

    auto load_idx = [&](unsigned lin) -> unsigned {
        if (is64) return (unsigned)((const unsigned long long*)indices)[lin] & (NPTS - 1);
        return ((const unsigned*)indices)[lin] & (NPTS - 1);
    };

    // ---- preload W2 A-fragments into registers (loop-invariant) ----
    uint32_t wa2[4][2][4];
#pragma unroll
    for (int ks = 0; ks < 4; ks++) {
        uint32_t ach = (2 * ks + (l >> 4)) * 16;
        ldsm4(wa2[ks][0], arow2 + ach);
        ldsm4(wa2[ks][1], arow2 + 16 * 144 + ach);
    }

    // ---- prologue: synchronous gather of tile0 into B1A ----
    const unsigned tile0 = blockIdx.x;
    {
        unsigned ii = load_idx(tile0 * TILE + gp);
        const char* src = (const char*)g_x + (size_t)ii * 128;
        uint32_t dst = sb + SM_B1A + gp * 176 + half * 64;
#pragma unroll
        for (int q = 0; q < 4; q++)
            CP16(dst + q * 16, src + half * 64 + q * 16);
        CP_COMMIT();
        if (tid < TILE) {
            unsigned ii2 = load_idx(tile0 * TILE + tid);
            unsigned m = tile0 * 8 + (tid >> 4);
            float p0 = pos[0 * NPTS + ii2] - sup[0 * MPTS + m];
            float p1 = pos[1 * NPTS + ii2] - sup[1 * MPTS + m];
            float p2 = pos[2 * NPTS + ii2] - sup[2 * MPTS + m];
            uint4 c8;
            c8.x = packh2(p0, p1);
            c8.y = packh2(p2, 1.0f);
            c8.z = 0u; c8.w = 0u;
            uint4 zz = make_uint4(0u, 0u, 0u, 0u);
            *(uint4*)(smc + SM_B1A + tid * 176 + 128) = c8;
            *(uint4*)(smc + SM_B1A + tid * 176 + 144) = zz;
        }
        CP_WAIT0();
    }
    __syncthreads();

    int bufsel = 0;
    for (unsigned tile = tile0; tile < NTILES; tile += GRID) {
        const uint32_t curB = bufsel ? SM_B1B : SM_B1A;
        const uint32_t nxtB = bufsel ? SM_B1A : SM_B1B;
        unsigned pf = tile + GRID;
        if (pf >= NTILES) pf = tile;                  // safe redundant prefetch

        // prefetch indices for tile+GRID (latency hidden by GEMM1)
        unsigned ii_nx = load_idx(pf * TILE + gp);
        unsigned ii_pd = 0;
        if (tid < TILE) ii_pd = load_idx(pf * TILE + tid);

        // ===== GEMM1: 64 x 128, K=80 (bias+pos folded), B pipelined =====
        {
            const uint32_t brow1 = sb + curB + boff1;
            float acc[2][4][4];
#pragma unroll
            for (int i = 0; i < 2; i++)
#pragma unroll
                for (int j = 0; j < 4; j++)
#pragma unroll
                    for (int q = 0; q < 4; q++) acc[i][j][q] = 0.0f;

            uint32_t b0[2][4], b1r[2][4];
            {   // preload ks=0 B fragments
                uint32_t bch = ((l >> 3) & 1) * 16;
                ldsm4(b0[0], brow1 + bch);
                ldsm4(b1r[0], brow1 + 16 * 176 + bch);
            }
#pragma unroll
            for (int ks = 0; ks < 5; ks++) {
                int cur = ks & 1, nxt = cur ^ 1;
                if (ks < 4) {   // prefetch next k-step's B
                    uint32_t bch = (2 * (ks + 1) + ((l >> 3) & 1)) * 16;
                    ldsm4(b0[nxt], brow1 + bch);
                    ldsm4(b1r[nxt], brow1 + 16 * 176 + bch);
                }
                uint32_t ach = (2 * ks + (l >> 4)) * 16;
                uint32_t a0[4], a1[4];
                ldsm4(a0, arow1 + ach);
                ldsm4(a1, arow1 + 16 * 176 + ach);
                mma_f32(acc[0][0], a0, b0[cur][0], b0[cur][1]);
                mma_f32(acc[0][1], a0, b0[cur][2], b0[cur][3]);
                mma_f32(acc[0][2], a0, b1r[cur][0], b1r[cur][1]);
                mma_f32(acc[0][3], a0, b1r[cur][2], b1r[cur][3]);
                mma_f32(acc[1][0], a1, b0[cur][0], b0[cur][1]);
                mma_f32(acc[1][1], a1, b0[cur][2], b0[cur][3]);
                mma_f32(acc[1][2], a1, b1r[cur][0], b1r[cur][1]);
                mma_f32(acc[1][3], a1, b1r[cur][2], b1r[cur][3]);
            }

            // ---- issue async gather of next tile into B1[nxt] ----
            {
                const char* src = (const char*)g_x + (size_t)ii_nx * 128;
                uint32_t dst = sb + nxtB + gp * 176 + half * 64;
#pragma unroll
                for (int q = 0; q < 4; q++)
                    CP16(dst + q * 16, src + half * 64 + q * 16);
                CP_COMMIT();
            }

            // ---- epilogue: relu -> fp16 -> H via stmatrix.trans ----
#pragma unroll
            for (int mb = 0; mb < 2; mb++) {
#pragma unroll
                for (int hf = 0; hf < 2; hf++) {
                    uint32_t r[4];
#pragma unroll
                    for (int nb = 0; nb < 4; nb++) {
                        float v0 = fmaxf(acc[mb][nb][2 * hf], 0.0f);
                        float v1 = fmaxf(acc[mb][nb][2 * hf + 1], 0.0f);
                        r[nb] = packh2(v0, v1);
                    }
                    uint32_t ch = 32 * (w & 1) + 16 * mb + 8 * hf;
                    stsm4t(hst + ch * 2, r[0], r[1], r[2], r[3]);
                }
            }
        }
        // H halves are written/read by the same 4-warp groups -> named barrier
        BARH(hbar);

        // ===== GEMM2: 128 x 128, K=64 (W2 in regs) + pool + direct output =====
        {
            float p0 = 0.f, p1 = 0.f, p2 = 0.f;
            if (tid < TILE) {
                unsigned m = pf * 8 + (tid >> 4);
                p0 = pos[0 * NPTS + ii_pd] - sup[0 * MPTS + m];
                p1 = pos[1 * NPTS + ii_pd] - sup[1 * MPTS + m];
                p2 = pos[2 * NPTS + ii_pd] - sup[2 * MPTS + m];
            }

            float acc[2][8][4];
#pragma unroll
            for (int i = 0; i < 2; i++)
#pragma unroll
                for (int j = 0; j < 8; j++)
#pragma unroll
                    for (int q = 0; q < 4; q++) acc[i][j][q] = 0.0f;

#pragma unroll
            for (int ks = 0; ks < 4; ks++) {
                uint32_t bch = (2 * ks + ((l >> 3) & 1)) * 16;
                uint32_t b[4][4];
#pragma unroll
                for (int nbq = 0; nbq < 4; nbq++)     // batch all loads first
                    ldsm4(b[nbq], brow2 + nbq * (16 * 144) + bch);
#pragma unroll
                for (int nbq = 0; nbq < 4; nbq++) {
                    mma_f32(acc[0][2 * nbq],     wa2[ks][0], b[nbq][0], b[nbq][1]);
                    mma_f32(acc[0][2 * nbq + 1], wa2[ks][0], b[nbq][2], b[nbq][3]);
                    mma_f32(acc[1][2 * nbq],     wa2[ks][1], b[nbq][0], b[nbq][1]);
                    mma_f32(acc[1][2 * nbq + 1], wa2[ks][1], b[nbq][2], b[nbq][3]);
                }
            }

            // ---- pool over K=16 + direct gmem output (lane quads) ----
#pragma unroll
            for (int mb = 0; mb < 2; mb++) {
                float r0[4], r1[4];
#pragma unroll
                for (int pt = 0; pt < 4; pt++) {
                    float m0 = fmaxf(fmaxf(acc[mb][2 * pt][0], acc[mb][2 * pt][1]),
                                     fmaxf(acc[mb][2 * pt + 1][0], acc[mb][2 * pt + 1][1]));
                    float m1 = fmaxf(fmaxf(acc[mb][2 * pt][2], acc[mb][2 * pt][3]),
                                     fmaxf(acc[mb][2 * pt + 1][2], acc[mb][2 * pt + 1][3]));
                    m0 = fmaxf(m0, __shfl_xor_sync(0xffffffffu, m0, 1));
                    m0 = fmaxf(m0, __shfl_xor_sync(0xffffffffu, m0, 2));
                    m1 = fmaxf(m1, __shfl_xor_sync(0xffffffffu, m1, 1));
                    m1 = fmaxf(m1, __shfl_xor_sync(0xffffffffu, m1, 2));
                    r0[pt] = m0; r1[pt] = m1;
                }
                if ((l & 3) == 0) {
                    float b0v = mb ? bo10 : bo00;
                    float b1v = mb ? bo11 : bo01;
                    int row = orow0 + 16 * mb;
                    float4 v0 = make_float4(r0[0] + b0v, r0[1] + b0v, r0[2] + b0v, r0[3] + b0v);
                    float4 v1 = make_float4(r1[0] + b1v, r1[1] + b1v, r1[2] + b1v, r1[3] + b1v);
                    *(float4*)(out + (size_t)row * MPTS + tile * 8 + mcol)       = v0;
                    *(float4*)(out + (size_t)(row + 8) * MPTS + tile * 8 + mcol) = v1;
                }
            }

            // ---- store next tile's pos channels into B1[nxt] ----
            if (tid < TILE) {
                uint4 c8;
                c8.x = packh2(p0, p1);
                c8.y = packh2(p2, 1.0f);
                c8.z = 0u; c8.w = 0u;
                uint4 zz = make_uint4(0u, 0u, 0u, 0u);
                *(uint4*)(smc + nxtB + tid * 176 + 128) = c8;
                *(uint4*)(smc + nxtB + tid * 176 + 144) = zz;
            }
        }

        CP_WAIT0();                       // B1[nxt] gather complete
        __syncthreads();                  // publish B1[nxt]; GEMM2->epi1(t+1) order
        bufsel ^= 1;
    }
}

// ---------------------------------------------------------------------------
extern "C" void kernel_launch(void* const* d_in, const int* in_sizes, int n_in,
                              void* d_out, int out_size)
{
    const float *x = 0, *pos = 0, *sup = 0, *W1 = 0, *b1 = 0, *W2 = 0, *b2 = 0;
    const void* idx = 0;
    for (int i = 0; i < n_in; i++) {
        switch (in_sizes[i]) {
            case 4194304: x  = (const float*)d_in[i]; break;
            case 196608:  if (!pos) pos = (const float*)d_in[i];
                          else      sup = (const float*)d_in[i]; break;
            case 4288:    W1 = (const float*)d_in[i]; break;
            case 64:      b1 = (const float*)d_in[i]; break;
            case 8192:    W2 = (const float*)d_in[i]; break;
            case 128:     b2 = (const float*)d_in[i]; break;
            case 1048576: idx = d_in[i]; break;
            default: break;
        }
    }
    float* out = (float*)d_out;

    prep_all_kernel<<<NPTS / 128, 256>>>(x, W1, b1, W2, (const unsigned int*)idx);

    cudaFuncSetAttribute(pointnet_mma_kernel,
                         cudaFuncAttributeMaxDynamicSharedMemorySize, SM_TOTAL);
    pointnet_mma_kernel<<<GRID, 256, SM_TOTAL>>>(pos, sup, b2, idx, out);
}

// round 15
// speedup vs baseline: 1.0596x; 1.0596x over previous
#include <cuda_runtime.h>
#include <cuda_fp16.h>
#include <cstdint>

#define NPTS 65536
#define MPTS 65536
#define KNB  16
#define TILE 128              // columns per CTA tile (8 pts x 16 nbrs)
#define NTILES 8192
#define GRID 296              // 2 CTAs per SM

// ---------------- device scratch ----------------
__device__ __align__(16) unsigned short g_x[(size_t)NPTS * 64];    // fp16 rows 128B
__device__ __align__(16) unsigned short g_w1e[64 * 80];            // W1|pos|bias|pad
__device__ __align__(16) unsigned short g_w2[128 * 64];
__device__ int g_idx_is64;

// ---------------- smem layout (bytes) ----------------
#define SM_W1   0                      // 64 * 176  = 11264
#define SM_W2   11264                  // 128 * 144 = 18432
#define SM_B1A  29696                  // 128 * 176 = 22528
#define SM_B1B  52224                  // 128 * 176 = 22528
#define SM_H    74752                  // 128 * 144 = 18432
#define SM_TOTAL 93184

// ---------------- helpers ----------------
__device__ __forceinline__ uint32_t smem_u32(const void* p) {
    uint32_t a;
    asm("{ .reg .u64 t; cvta.to.shared.u64 t, %1; cvt.u32.u64 %0, t; }" : "=r"(a) : "l"(p));
    return a;
}
__device__ __forceinline__ void ldsm4(uint32_t (&r)[4], uint32_t addr) {
    asm volatile("ldmatrix.sync.aligned.m8n8.x4.shared.b16 {%0,%1,%2,%3}, [%4];"
                 : "=r"(r[0]), "=r"(r[1]), "=r"(r[2]), "=r"(r[3]) : "r"(addr));
}
__device__ __forceinline__ void stsm4t(uint32_t addr, uint32_t r0, uint32_t r1,
                                       uint32_t r2, uint32_t r3) {
    asm volatile("stmatrix.sync.aligned.m8n8.x4.trans.shared.b16 [%0], {%1,%2,%3,%4};"
                 :: "r"(addr), "r"(r0), "r"(r1), "r"(r2), "r"(r3) : "memory");
}
__device__ __forceinline__ void mma_f32(float (&d)[4], const uint32_t (&a)[4],
                                        uint32_t b0, uint32_t b1) {
    asm volatile("mma.sync.aligned.m16n8k16.row.col.f32.f16.f16.f32 "
                 "{%0,%1,%2,%3}, {%4,%5,%6,%7}, {%8,%9}, {%0,%1,%2,%3};"
                 : "+f"(d[0]), "+f"(d[1]), "+f"(d[2]), "+f"(d[3])
                 : "r"(a[0]), "r"(a[1]), "r"(a[2]), "r"(a[3]), "r"(b0), "r"(b1));
}
#define CP16(dst, src) \
    asm volatile("cp.async.cg.shared.global [%0], [%1], 16;" :: "r"(dst), "l"(src))
#define CP_COMMIT()  asm volatile("cp.async.commit_group;" ::: "memory")
#define CP_WAIT0()   asm volatile("cp.async.wait_group 0;" ::: "memory")
#define BARQ(id)     asm volatile("bar.sync %0, 128;" :: "r"(id) : "memory")

__device__ __forceinline__ uint32_t packh2(float a, float b) {
    __half2 h = __floats2half2_rn(a, b);
    return *(uint32_t*)&h;
}

// ---------------- prep ----------------
__global__ __launch_bounds__(256) void prep_all_kernel(const float* __restrict__ x,
                                                       const float* __restrict__ W1,
                                                       const float* __restrict__ b1,
                                                       const float* __restrict__ W2,
                                                       const unsigned int* __restrict__ idx32)
{
    __shared__ unsigned short shhi[128 * 72];
    const int p0 = blockIdx.x * 128;
    const int tid = threadIdx.x;

    for (int idx = tid; idx < 128 * 64; idx += 256) {
        int c = idx >> 7, p = idx & 127;
        float v = x[(size_t)c * NPTS + p0 + p];
        shhi[p * 72 + c] = __half_as_ushort(__float2half_rn(v));
    }

    if (blockIdx.x == 0) {
        if (tid == 0) {
            unsigned int orv = 0;
            for (int i = 0; i < 256; i++) orv |= idx32[2 * i + 1];
            g_idx_is64 = (orv == 0u) ? 1 : 0;
        }
        for (int i = tid; i < 64 * 80; i += 256) {
            int o = i / 80, c = i % 80;
            float v = 0.0f;
            if (c < 67)       v = W1[o * 67 + c];
            else if (c == 67) v = b1[o];
            g_w1e[i] = __half_as_ushort(__float2half_rn(v));
        }
        for (int i = tid; i < 128 * 64; i += 256)
            g_w2[i] = __half_as_ushort(__float2half_rn(W2[i]));
    }
    __syncthreads();
    uint4* dh = (uint4*)(g_x + (size_t)p0 * 64);
    for (int i = tid; i < 1024; i += 256) {
        int p = i >> 3, q = i & 7;
        dh[i] = *(const uint4*)&shhi[p * 72 + q * 8];
    }
}

// ---------------- main persistent kernel: 256 thr, 2 CTAs/SM ----------------
// Tile dataflow is block-diagonal over two 4-warp quads (warps 0-3, 4-7):
// quad q gathers/consumes B1 rows [64q,64q+64), writes/reads H rows [64q,+64),
// and writes warp-local outputs. Only 128-thread named barriers are needed
// inside the loop -> 4 independent quad pipelines per SM.
extern __shared__ char smc[];

__global__ __launch_bounds__(256, 2)
void pointnet_mma_kernel(const float* __restrict__ pos,
                         const float* __restrict__ sup,
                         const float* __restrict__ b2,
                         const void* __restrict__ indices,
                         float* __restrict__ out)
{
    const uint32_t sb = smem_u32(smc);
    const int tid = threadIdx.x;
    const int w = tid >> 5;
    const int l = tid & 31;
    const int is64 = g_idx_is64;

    // ---- stage weights once ----
    for (int i = tid; i < 640; i += 256) {            // W1e: 64 rows x 10 chunks
        int o = i / 10, c = i % 10;
        *(uint4*)(smc + SM_W1 + o * 176 + c * 16) = *(const uint4*)(g_w1e + o * 80 + c * 8);
    }
    for (int i = tid; i < 1024; i += 256) {           // W2: 128 rows x 8 chunks
        int o = i >> 3, c = i & 7;
        *(uint4*)(smc + SM_W2 + o * 144 + c * 16) = *(const uint4*)(g_w2 + o * 64 + c * 8);
    }
    __syncthreads();

    // ---- loop-invariant constants ----
    const int qq = tid >> 7;                          // quad id (0/1) == w>>2
    const int qlocal = tid & 127;
    const int qbar = 1 + qq;                          // named barrier per quad

    const uint32_t arow1 = sb + SM_W1 + (32 * (w & 1) + ((l >> 3) & 1) * 8 + (l & 7)) * 176;
    const uint32_t boff1 = (uint32_t)(32 * (w >> 1) + ((l >> 4) & 1) * 8 + (l & 7)) * 176;
    const uint32_t arow2 = sb + SM_W2 + (32 * (w & 3) + ((l >> 3) & 1) * 8 + (l & 7)) * 144;
    const uint32_t brow2 = sb + SM_H  + (64 * qq + ((l >> 4) & 1) * 8 + (l & 7)) * 144;
    const uint32_t hst   = sb + SM_H + (32 * (w >> 1) + 8 * (l >> 3) + (l & 7)) * 144;

    // output rows owned by this lane + biases
    const int orow0 = 32 * (w & 3) + (l >> 2);
    const int mcol  = 4 * qq;
    const float bo00 = __ldg(&b2[orow0]);
    const float bo01 = __ldg(&b2[orow0 + 8]);
    const float bo10 = __ldg(&b2[orow0 + 16]);
    const float bo11 = __ldg(&b2[orow0 + 24]);

    // quad-local gather mapping: rows [64*qq, 64*qq+64)
    const unsigned grow = 64 * qq + (qlocal >> 1);    // B1 row this thread fills
    const unsigned half = qlocal & 1;
    const unsigned prow = 64 * qq + (qlocal & 63);    // pos row (qlocal<64 only)
    const bool     dopos = qlocal < 64;

    auto load_idx = [&](unsigned lin) -> unsigned {
        if (is64) return (unsigned)((const unsigned long long*)indices)[lin] & (NPTS - 1);
        return ((const unsigned*)indices)[lin] & (NPTS - 1);
    };

    // ---- preload W2 A-fragments into registers (loop-invariant) ----
    uint32_t wa2[4][2][4];
#pragma unroll
    for (int ks = 0; ks < 4; ks++) {
        uint32_t ach = (2 * ks + (l >> 4)) * 16;
        ldsm4(wa2[ks][0], arow2 + ach);
        ldsm4(wa2[ks][1], arow2 + 16 * 144 + ach);
    }

    // ---- prologue: synchronous gather of tile0 into B1A ----
    const unsigned tile0 = blockIdx.x;
    {
        unsigned ii = load_idx(tile0 * TILE + grow);
        const char* src = (const char*)g_x + (size_t)ii * 128;
        uint32_t dst = sb + SM_B1A + grow * 176 + half * 64;
#pragma unroll
        for (int q = 0; q < 4; q++)
            CP16(dst + q * 16, src + half * 64 + q * 16);
        CP_COMMIT();
        if (dopos) {
            unsigned ii2 = load_idx(tile0 * TILE + prow);
            unsigned m = tile0 * 8 + (prow >> 4);
            float p0 = pos[0 * NPTS + ii2] - sup[0 * MPTS + m];
            float p1 = pos[1 * NPTS + ii2] - sup[1 * MPTS + m];
            float p2 = pos[2 * NPTS + ii2] - sup[2 * MPTS + m];
            uint4 c8;
            c8.x = packh2(p0, p1);
            c8.y = packh2(p2, 1.0f);
            c8.z = 0u; c8.w = 0u;
            uint4 zz = make_uint4(0u, 0u, 0u, 0u);
            *(uint4*)(smc + SM_B1A + prow * 176 + 128) = c8;
            *(uint4*)(smc + SM_B1A + prow * 176 + 144) = zz;
        }
        CP_WAIT0();
    }
    __syncthreads();

    int bufsel = 0;
    for (unsigned tile = tile0; tile < NTILES; tile += GRID) {
        const uint32_t curB = bufsel ? SM_B1B : SM_B1A;
        const uint32_t nxtB = bufsel ? SM_B1A : SM_B1B;
        unsigned pf = tile + GRID;
        if (pf >= NTILES) pf = tile;                  // safe redundant prefetch

        // prefetch indices for tile+GRID (latency hidden by GEMM1)
        unsigned ii_nx = load_idx(pf * TILE + grow);
        unsigned ii_pd = 0;
        if (dopos) ii_pd = load_idx(pf * TILE + prow);

        // ===== GEMM1: 64 x 128, K=80 (bias+pos folded), B pipelined =====
        {
            const uint32_t brow1 = sb + curB + boff1;
            float acc[2][4][4];
#pragma unroll
            for (int i = 0; i < 2; i++)
#pragma unroll
                for (int j = 0; j < 4; j++)
#pragma unroll
                    for (int q = 0; q < 4; q++) acc[i][j][q] = 0.0f;

            uint32_t b0[2][4], b1r[2][4];
            {   // preload ks=0 B fragments
                uint32_t bch = ((l >> 3) & 1) * 16;
                ldsm4(b0[0], brow1 + bch);
                ldsm4(b1r[0], brow1 + 16 * 176 + bch);
            }
#pragma unroll
            for (int ks = 0; ks < 5; ks++) {
                int cur = ks & 1, nxt = cur ^ 1;
                if (ks < 4) {   // prefetch next k-step's B
                    uint32_t bch = (2 * (ks + 1) + ((l >> 3) & 1)) * 16;
                    ldsm4(b0[nxt], brow1 + bch);
                    ldsm4(b1r[nxt], brow1 + 16 * 176 + bch);
                }
                uint32_t ach = (2 * ks + (l >> 4)) * 16;
                uint32_t a0[4], a1[4];
                ldsm4(a0, arow1 + ach);
                ldsm4(a1, arow1 + 16 * 176 + ach);
                mma_f32(acc[0][0], a0, b0[cur][0], b0[cur][1]);
                mma_f32(acc[0][1], a0, b0[cur][2], b0[cur][3]);
                mma_f32(acc[0][2], a0, b1r[cur][0], b1r[cur][1]);
                mma_f32(acc[0][3], a0, b1r[cur][2], b1r[cur][3]);
                mma_f32(acc[1][0], a1, b0[cur][0], b0[cur][1]);
                mma_f32(acc[1][1], a1, b0[cur][2], b0[cur][3]);
                mma_f32(acc[1][2], a1, b1r[cur][0], b1r[cur][1]);
                mma_f32(acc[1][3], a1, b1r[cur][2], b1r[cur][3]);
            }

            // ---- issue async gather of next tile into B1[nxt] (quad rows) ----
            {
                const char* src = (const char*)g_x + (size_t)ii_nx * 128;
                uint32_t dst = sb + nxtB + grow * 176 + half * 64;
#pragma unroll
                for (int q = 0; q < 4; q++)
                    CP16(dst + q * 16, src + half * 64 + q * 16);
                CP_COMMIT();
            }

            // ---- epilogue: relu -> fp16 -> H via stmatrix.trans ----
#pragma unroll
            for (int mb = 0; mb < 2; mb++) {
#pragma unroll
                for (int hf = 0; hf < 2; hf++) {
                    uint32_t r[4];
#pragma unroll
                    for (int nb = 0; nb < 4; nb++) {
                        float v0 = fmaxf(acc[mb][nb][2 * hf], 0.0f);
                        float v1 = fmaxf(acc[mb][nb][2 * hf + 1], 0.0f);
                        r[nb] = packh2(v0, v1);
                    }
                    uint32_t ch = 32 * (w & 1) + 16 * mb + 8 * hf;
                    stsm4t(hst + ch * 2, r[0], r[1], r[2], r[3]);
                }
            }
        }
        BARQ(qbar);            // H(t) writes visible to quad before GEMM2 reads

        // ===== GEMM2: 128 x 128, K=64 (W2 in regs) + pool + direct output =====
        {
            float p0 = 0.f, p1 = 0.f, p2 = 0.f;
            if (dopos) {
                unsigned m = pf * 8 + (prow >> 4);
                p0 = pos[0 * NPTS + ii_pd] - sup[0 * MPTS + m];
                p1 = pos[1 * NPTS + ii_pd] - sup[1 * MPTS + m];
                p2 = pos[2 * NPTS + ii_pd] - sup[2 * MPTS + m];
            }

            float acc[2][8][4];
#pragma unroll
            for (int i = 0; i < 2; i++)
#pragma unroll
                for (int j = 0; j < 8; j++)
#pragma unroll
                    for (int q = 0; q < 4; q++) acc[i][j][q] = 0.0f;

#pragma unroll
            for (int ks = 0; ks < 4; ks++) {
                uint32_t bch = (2 * ks + ((l >> 3) & 1)) * 16;
                uint32_t b[4][4];
#pragma unroll
                for (int nbq = 0; nbq < 4; nbq++)     // batch all loads first
                    ldsm4(b[nbq], brow2 + nbq * (16 * 144) + bch);
#pragma unroll
                for (int nbq = 0; nbq < 4; nbq++) {
                    mma_f32(acc[0][2 * nbq],     wa2[ks][0], b[nbq][0], b[nbq][1]);
                    mma_f32(acc[0][2 * nbq + 1], wa2[ks][0], b[nbq][2], b[nbq][3]);
                    mma_f32(acc[1][2 * nbq],     wa2[ks][1], b[nbq][0], b[nbq][1]);
                    mma_f32(acc[1][2 * nbq + 1], wa2[ks][1], b[nbq][2], b[nbq][3]);
                }
            }

            // ---- pool over K=16 + direct gmem output (lane quads) ----
#pragma unroll
            for (int mb = 0; mb < 2; mb++) {
                float r0[4], r1[4];
#pragma unroll
                for (int pt = 0; pt < 4; pt++) {
                    float m0 = fmaxf(fmaxf(acc[mb][2 * pt][0], acc[mb][2 * pt][1]),
                                     fmaxf(acc[mb][2 * pt + 1][0], acc[mb][2 * pt + 1][1]));
                    float m1 = fmaxf(fmaxf(acc[mb][2 * pt][2], acc[mb][2 * pt][3]),
                                     fmaxf(acc[mb][2 * pt + 1][2], acc[mb][2 * pt + 1][3]));
                    m0 = fmaxf(m0, __shfl_xor_sync(0xffffffffu, m0, 1));
                    m0 = fmaxf(m0, __shfl_xor_sync(0xffffffffu, m0, 2));
                    m1 = fmaxf(m1, __shfl_xor_sync(0xffffffffu, m1, 1));
                    m1 = fmaxf(m1, __shfl_xor_sync(0xffffffffu, m1, 2));
                    r0[pt] = m0; r1[pt] = m1;
                }
                if ((l & 3) == 0) {
                    float b0v = mb ? bo10 : bo00;
                    float b1v = mb ? bo11 : bo01;
                    int row = orow0 + 16 * mb;
                    float4 v0 = make_float4(r0[0] + b0v, r0[1] + b0v, r0[2] + b0v, r0[3] + b0v);
                    float4 v1 = make_float4(r1[0] + b1v, r1[1] + b1v, r1[2] + b1v, r1[3] + b1v);
                    *(float4*)(out + (size_t)row * MPTS + tile * 8 + mcol)       = v0;
                    *(float4*)(out + (size_t)(row + 8) * MPTS + tile * 8 + mcol) = v1;
                }
            }

            // ---- store next tile's pos channels into B1[nxt] (quad rows) ----
            if (dopos) {
                uint4 c8;
                c8.x = packh2(p0, p1);
                c8.y = packh2(p2, 1.0f);
                c8.z = 0u; c8.w = 0u;
                uint4 zz = make_uint4(0u, 0u, 0u, 0u);
                *(uint4*)(smc + nxtB + prow * 176 + 128) = c8;
                *(uint4*)(smc + nxtB + prow * 176 + 144) = zz;
            }
        }

        CP_WAIT0();            // this thread's B1[nxt] chunks complete
        BARQ(qbar);            // quad: B1[nxt]+pos published; H(t) reads done
        bufsel ^= 1;
    }
}

// ---------------------------------------------------------------------------
extern "C" void kernel_launch(void* const* d_in, const int* in_sizes, int n_in,
                              void* d_out, int out_size)
{
    const float *x = 0, *pos = 0, *sup = 0, *W1 = 0, *b1 = 0, *W2 = 0, *b2 = 0;
    const void* idx = 0;
    for (int i = 0; i < n_in; i++) {
        switch (in_sizes[i]) {
            case 4194304: x  = (const float*)d_in[i]; break;
            case 196608:  if (!pos) pos = (const float*)d_in[i];
                          else      sup = (const float*)d_in[i]; break;
            case 4288:    W1 = (const float*)d_in[i]; break;
            case 64:      b1 = (const float*)d_in[i]; break;
            case 8192:    W2 = (const float*)d_in[i]; break;
            case 128:     b2 = (const float*)d_in[i]; break;
            case 1048576: idx = d_in[i]; break;
            default: break;
        }
    }
    float* out = (float*)d_out;

    prep_all_kernel<<<NPTS / 128, 256>>>(x, W1, b1, W2, (const unsigned int*)idx);

    cudaFuncSetAttribute(pointnet_mma_kernel,
                         cudaFuncAttributeMaxDynamicSharedMemorySize, SM_TOTAL);
    pointnet_mma_kernel<<<GRID, 256, SM_TOTAL>>>(pos, sup, b2, idx, out);
}

// round 16
// speedup vs baseline: 1.1000x; 1.0381x over previous
#include <cuda_runtime.h>
#include <cuda_fp16.h>
#include <cstdint>

#define NPTS 65536
#define MPTS 65536
#define KNB  16
#define TILE 128              // columns per CTA tile (8 pts x 16 nbrs)
#define NTILES 8192
#define GRID 296              // 2 CTAs per SM

// ---------------- device scratch ----------------
__device__ __align__(16) unsigned short g_x[(size_t)NPTS * 64];    // fp16 rows 128B
__device__ __align__(16) unsigned short g_w1e[64 * 80];            // W1|pos|bias|pad
__device__ __align__(16) unsigned short g_w2[128 * 64];
__device__ int g_idx_is64;

// ---------------- smem layout (bytes) ----------------
#define SM_W1   0                      // 64 * 176  = 11264
#define SM_W2   11264                  // 128 * 144 = 18432
#define SM_B1A  29696                  // 128 * 176 = 22528
#define SM_B1B  52224                  // 128 * 176 = 22528
#define SM_H    74752                  // 128 * 144 = 18432
#define SM_TOTAL 93184

// ---------------- helpers ----------------
__device__ __forceinline__ uint32_t smem_u32(const void* p) {
    uint32_t a;
    asm("{ .reg .u64 t; cvta.to.shared.u64 t, %1; cvt.u32.u64 %0, t; }" : "=r"(a) : "l"(p));
    return a;
}
__device__ __forceinline__ void ldsm4(uint32_t (&r)[4], uint32_t addr) {
    asm volatile("ldmatrix.sync.aligned.m8n8.x4.shared.b16 {%0,%1,%2,%3}, [%4];"
                 : "=r"(r[0]), "=r"(r[1]), "=r"(r[2]), "=r"(r[3]) : "r"(addr));
}
__device__ __forceinline__ void stsm4t(uint32_t addr, uint32_t r0, uint32_t r1,
                                       uint32_t r2, uint32_t r3) {
    asm volatile("stmatrix.sync.aligned.m8n8.x4.trans.shared.b16 [%0], {%1,%2,%3,%4};"
                 :: "r"(addr), "r"(r0), "r"(r1), "r"(r2), "r"(r3) : "memory");
}
__device__ __forceinline__ void mma_f32(float (&d)[4], const uint32_t (&a)[4],
                                        uint32_t b0, uint32_t b1) {
    asm volatile("mma.sync.aligned.m16n8k16.row.col.f32.f16.f16.f32 "
                 "{%0,%1,%2,%3}, {%4,%5,%6,%7}, {%8,%9}, {%0,%1,%2,%3};"
                 : "+f"(d[0]), "+f"(d[1]), "+f"(d[2]), "+f"(d[3])
                 : "r"(a[0]), "r"(a[1]), "r"(a[2]), "r"(a[3]), "r"(b0), "r"(b1));
}
#define CP16(dst, src) \
    asm volatile("cp.async.cg.shared.global [%0], [%1], 16;" :: "r"(dst), "l"(src))
#define CP_COMMIT()  asm volatile("cp.async.commit_group;" ::: "memory")
#define CP_WAIT0()   asm volatile("cp.async.wait_group 0;" ::: "memory")
#define BARQ(id)     asm volatile("bar.sync %0, 128;" :: "r"(id) : "memory")

__device__ __forceinline__ uint32_t packh2(float a, float b) {
    __half2 h = __floats2half2_rn(a, b);
    return *(uint32_t*)&h;
}

// ---------------- prep ----------------
__global__ __launch_bounds__(256) void prep_all_kernel(const float* __restrict__ x,
                                                       const float* __restrict__ W1,
                                                       const float* __restrict__ b1,
                                                       const float* __restrict__ W2,
                                                       const unsigned int* __restrict__ idx32)
{
    __shared__ unsigned short shhi[128 * 72];
    const int p0 = blockIdx.x * 128;
    const int tid = threadIdx.x;

    for (int idx = tid; idx < 128 * 64; idx += 256) {
        int c = idx >> 7, p = idx & 127;
        float v = x[(size_t)c * NPTS + p0 + p];
        shhi[p * 72 + c] = __half_as_ushort(__float2half_rn(v));
    }

    if (blockIdx.x == 0) {
        if (tid == 0) {
            unsigned int orv = 0;
            for (int i = 0; i < 256; i++) orv |= idx32[2 * i + 1];
            g_idx_is64 = (orv == 0u) ? 1 : 0;
        }
        for (int i = tid; i < 64 * 80; i += 256) {
            int o = i / 80, c = i % 80;
            float v = 0.0f;
            if (c < 67)       v = W1[o * 67 + c];
            else if (c == 67) v = b1[o];
            g_w1e[i] = __half_as_ushort(__float2half_rn(v));
        }
        for (int i = tid; i < 128 * 64; i += 256)
            g_w2[i] = __half_as_ushort(__float2half_rn(W2[i]));
    }
    __syncthreads();
    uint4* dh = (uint4*)(g_x + (size_t)p0 * 64);
    for (int i = tid; i < 1024; i += 256) {
        int p = i >> 3, q = i & 7;
        dh[i] = *(const uint4*)&shhi[p * 72 + q * 8];
    }
}

// ---------------- main persistent kernel: 256 thr, 2 CTAs/SM ----------------
// Tile dataflow is block-diagonal over two 4-warp quads; quad-local named
// barriers only. GEMM2 pools early (n-outer) to cut register pressure.
extern __shared__ char smc[];

__global__ __launch_bounds__(256, 2)
void pointnet_mma_kernel(const float* __restrict__ pos,
                         const float* __restrict__ sup,
                         const float* __restrict__ b2,
                         const void* __restrict__ indices,
                         float* __restrict__ out)
{
    const uint32_t sb = smem_u32(smc);
    const int tid = threadIdx.x;
    const int w = tid >> 5;
    const int l = tid & 31;
    const int is64 = g_idx_is64;

    // ---- stage weights once ----
    for (int i = tid; i < 640; i += 256) {            // W1e: 64 rows x 10 chunks
        int o = i / 10, c = i % 10;
        *(uint4*)(smc + SM_W1 + o * 176 + c * 16) = *(const uint4*)(g_w1e + o * 80 + c * 8);
    }
    for (int i = tid; i < 1024; i += 256) {           // W2: 128 rows x 8 chunks
        int o = i >> 3, c = i & 7;
        *(uint4*)(smc + SM_W2 + o * 144 + c * 16) = *(const uint4*)(g_w2 + o * 64 + c * 8);
    }

    // ---- loop-invariant constants ----
    const int qq = tid >> 7;                          // quad id (0/1) == w>>2
    const int qlocal = tid & 127;
    const int qbar = 1 + qq;                          // named barrier per quad

    const uint32_t arow1 = sb + SM_W1 + (32 * (w & 1) + ((l >> 3) & 1) * 8 + (l & 7)) * 176;
    const uint32_t boff1 = (uint32_t)(32 * (w >> 1) + ((l >> 4) & 1) * 8 + (l & 7)) * 176;
    const uint32_t arow2 = sb + SM_W2 + (32 * (w & 3) + ((l >> 3) & 1) * 8 + (l & 7)) * 144;
    const uint32_t brow2 = sb + SM_H  + (64 * qq + ((l >> 4) & 1) * 8 + (l & 7)) * 144;
    const uint32_t hst   = sb + SM_H + (32 * (w >> 1) + 8 * (l >> 3) + (l & 7)) * 144;

    // output rows owned by this lane + biases
    const int orow0 = 32 * (w & 3) + (l >> 2);
    const int mcol  = 4 * qq;
    const float bo00 = __ldg(&b2[orow0]);
    const float bo01 = __ldg(&b2[orow0 + 8]);
    const float bo10 = __ldg(&b2[orow0 + 16]);
    const float bo11 = __ldg(&b2[orow0 + 24]);

    // quad-local gather mapping: rows [64*qq, 64*qq+64)
    const unsigned grow = 64 * qq + (qlocal >> 1);    // B1 row this thread fills
    const unsigned half = qlocal & 1;
    const unsigned prow = 64 * qq + (qlocal & 63);    // pos row (qlocal<64 only)
    const bool     dopos = qlocal < 64;

    auto load_idx = [&](unsigned lin) -> unsigned {
        if (is64) return (unsigned)((const unsigned long long*)indices)[lin] & (NPTS - 1);
        return ((const unsigned*)indices)[lin] & (NPTS - 1);
    };

    // ---- write constant zero pad (channels 72-79) once for BOTH buffers ----
    if (dopos) {
        uint4 zz = make_uint4(0u, 0u, 0u, 0u);
        *(uint4*)(smc + SM_B1A + prow * 176 + 144) = zz;
        *(uint4*)(smc + SM_B1B + prow * 176 + 144) = zz;
    }
    __syncthreads();

    // ---- preload W2 A-fragments into registers (loop-invariant) ----
    uint32_t wa2[4][2][4];
#pragma unroll
    for (int ks = 0; ks < 4; ks++) {
        uint32_t ach = (2 * ks + (l >> 4)) * 16;
        ldsm4(wa2[ks][0], arow2 + ach);
        ldsm4(wa2[ks][1], arow2 + 16 * 144 + ach);
    }

    // ---- prologue: synchronous gather of tile0 into B1A ----
    const unsigned tile0 = blockIdx.x;
    {
        unsigned ii = load_idx(tile0 * TILE + grow);
        const char* src = (const char*)g_x + (size_t)ii * 128;
        uint32_t dst = sb + SM_B1A + grow * 176 + half * 64;
#pragma unroll
        for (int q = 0; q < 4; q++)
            CP16(dst + q * 16, src + half * 64 + q * 16);
        CP_COMMIT();
        if (dopos) {
            unsigned ii2 = load_idx(tile0 * TILE + prow);
            unsigned m = tile0 * 8 + (prow >> 4);
            float p0 = pos[0 * NPTS + ii2] - sup[0 * MPTS + m];
            float p1 = pos[1 * NPTS + ii2] - sup[1 * MPTS + m];
            float p2 = pos[2 * NPTS + ii2] - sup[2 * MPTS + m];
            uint4 c8;
            c8.x = packh2(p0, p1);
            c8.y = packh2(p2, 1.0f);
            c8.z = 0u; c8.w = 0u;
            *(uint4*)(smc + SM_B1A + prow * 176 + 128) = c8;
        }
        CP_WAIT0();
    }
    __syncthreads();

    int bufsel = 0;
    for (unsigned tile = tile0; tile < NTILES; tile += GRID) {
        const uint32_t curB = bufsel ? SM_B1B : SM_B1A;
        const uint32_t nxtB = bufsel ? SM_B1A : SM_B1B;
        unsigned pf = tile + GRID;
        if (pf >= NTILES) pf = tile;                  // safe redundant prefetch

        // prefetch indices for tile+GRID (latency hidden by GEMM1)
        unsigned ii_nx = load_idx(pf * TILE + grow);
        unsigned ii_pd = 0;
        if (dopos) ii_pd = load_idx(pf * TILE + prow);

        // ===== GEMM1: 64 x 128, K=80 (bias+pos folded), B pipelined =====
        {
            const uint32_t brow1 = sb + curB + boff1;
            float acc[2][4][4];
#pragma unroll
            for (int i = 0; i < 2; i++)
#pragma unroll
                for (int j = 0; j < 4; j++)
#pragma unroll
                    for (int q = 0; q < 4; q++) acc[i][j][q] = 0.0f;

            uint32_t b0[2][4], b1r[2][4];
            {   // preload ks=0 B fragments
                uint32_t bch = ((l >> 3) & 1) * 16;
                ldsm4(b0[0], brow1 + bch);
                ldsm4(b1r[0], brow1 + 16 * 176 + bch);
            }
#pragma unroll
            for (int ks = 0; ks < 5; ks++) {
                int cur = ks & 1, nxt = cur ^ 1;
                if (ks < 4) {   // prefetch next k-step's B
                    uint32_t bch = (2 * (ks + 1) + ((l >> 3) & 1)) * 16;
                    ldsm4(b0[nxt], brow1 + bch);
                    ldsm4(b1r[nxt], brow1 + 16 * 176 + bch);
                }
                uint32_t ach = (2 * ks + (l >> 4)) * 16;
                uint32_t a0[4], a1[4];
                ldsm4(a0, arow1 + ach);
                ldsm4(a1, arow1 + 16 * 176 + ach);
                mma_f32(acc[0][0], a0, b0[cur][0], b0[cur][1]);
                mma_f32(acc[0][1], a0, b0[cur][2], b0[cur][3]);
                mma_f32(acc[0][2], a0, b1r[cur][0], b1r[cur][1]);
                mma_f32(acc[0][3], a0, b1r[cur][2], b1r[cur][3]);
                mma_f32(acc[1][0], a1, b0[cur][0], b0[cur][1]);
                mma_f32(acc[1][1], a1, b0[cur][2], b0[cur][3]);
                mma_f32(acc[1][2], a1, b1r[cur][0], b1r[cur][1]);
                mma_f32(acc[1][3], a1, b1r[cur][2], b1r[cur][3]);
            }

            // ---- issue async gather of next tile into B1[nxt] (quad rows) ----
            {
                const char* src = (const char*)g_x + (size_t)ii_nx * 128;
                uint32_t dst = sb + nxtB + grow * 176 + half * 64;
#pragma unroll
                for (int q = 0; q < 4; q++)
                    CP16(dst + q * 16, src + half * 64 + q * 16);
                CP_COMMIT();
            }

            // ---- epilogue: relu -> fp16 -> H via stmatrix.trans ----
#pragma unroll
            for (int mb = 0; mb < 2; mb++) {
#pragma unroll
                for (int hf = 0; hf < 2; hf++) {
                    uint32_t r[4];
#pragma unroll
                    for (int nb = 0; nb < 4; nb++) {
                        float v0 = fmaxf(acc[mb][nb][2 * hf], 0.0f);
                        float v1 = fmaxf(acc[mb][nb][2 * hf + 1], 0.0f);
                        r[nb] = packh2(v0, v1);
                    }
                    uint32_t ch = 32 * (w & 1) + 16 * mb + 8 * hf;
                    stsm4t(hst + ch * 2, r[0], r[1], r[2], r[3]);
                }
            }
        }
        BARQ(qbar);            // H(t) writes visible to quad before GEMM2 reads

        // ===== GEMM2: n-outer early-pool, B pipelined, W2 in regs =====
        {
            float p0 = 0.f, p1 = 0.f, p2 = 0.f;
            if (dopos) {
                unsigned m = pf * 8 + (prow >> 4);
                p0 = pos[0 * NPTS + ii_pd] - sup[0 * MPTS + m];
                p1 = pos[1 * NPTS + ii_pd] - sup[1 * MPTS + m];
                p2 = pos[2 * NPTS + ii_pd] - sup[2 * MPTS + m];
            }

            float pr0[2][4], pr1[2][4];               // pooled per mb per point
            uint32_t bfr[2][4];
            {   // preload (nbq=0, ks=0)
                uint32_t bch = ((l >> 3) & 1) * 16;
                ldsm4(bfr[0], brow2 + bch);
            }
#pragma unroll
            for (int nbq = 0; nbq < 4; nbq++) {
                float acc[2][2][4];
#pragma unroll
                for (int i = 0; i < 2; i++)
#pragma unroll
                    for (int j = 0; j < 2; j++)
#pragma unroll
                        for (int q = 0; q < 4; q++) acc[i][j][q] = 0.0f;

#pragma unroll
                for (int ks = 0; ks < 4; ks++) {
                    int it = nbq * 4 + ks;
                    int cur = it & 1, nxt = cur ^ 1;
                    if (it < 15) {                    // prefetch next (nbq,ks)
                        int jt = it + 1;
                        uint32_t bch = (2 * (jt & 3) + ((l >> 3) & 1)) * 16;
                        ldsm4(bfr[nxt], brow2 + (uint32_t)(jt >> 2) * (16 * 144) + bch);
                    }
                    mma_f32(acc[0][0], wa2[ks][0], bfr[cur][0], bfr[cur][1]);
                    mma_f32(acc[0][1], wa2[ks][0], bfr[cur][2], bfr[cur][3]);
                    mma_f32(acc[1][0], wa2[ks][1], bfr[cur][0], bfr[cur][1]);
                    mma_f32(acc[1][1], wa2[ks][1], bfr[cur][2], bfr[cur][3]);
                }
                // early pool: this nbq = one support point's 16 columns
#pragma unroll
                for (int mb = 0; mb < 2; mb++) {
                    pr0[mb][nbq] = fmaxf(fmaxf(acc[mb][0][0], acc[mb][0][1]),
                                         fmaxf(acc[mb][1][0], acc[mb][1][1]));
                    pr1[mb][nbq] = fmaxf(fmaxf(acc[mb][0][2], acc[mb][0][3]),
                                         fmaxf(acc[mb][1][2], acc[mb][1][3]));
                }
            }

            // ---- lane-quad reduce + direct gmem output ----
#pragma unroll
            for (int mb = 0; mb < 2; mb++) {
                float r0[4], r1[4];
#pragma unroll
                for (int pt = 0; pt < 4; pt++) {
                    float m0 = pr0[mb][pt];
                    float m1 = pr1[mb][pt];
                    m0 = fmaxf(m0, __shfl_xor_sync(0xffffffffu, m0, 1));
                    m0 = fmaxf(m0, __shfl_xor_sync(0xffffffffu, m0, 2));
                    m1 = fmaxf(m1, __shfl_xor_sync(0xffffffffu, m1, 1));
                    m1 = fmaxf(m1, __shfl_xor_sync(0xffffffffu, m1, 2));
                    r0[pt] = m0; r1[pt] = m1;
                }
                if ((l & 3) == 0) {
                    float b0v = mb ? bo10 : bo00;
                    float b1v = mb ? bo11 : bo01;
                    int row = orow0 + 16 * mb;
                    float4 v0 = make_float4(r0[0] + b0v, r0[1] + b0v, r0[2] + b0v, r0[3] + b0v);
                    float4 v1 = make_float4(r1[0] + b1v, r1[1] + b1v, r1[2] + b1v, r1[3] + b1v);
                    *(float4*)(out + (size_t)row * MPTS + tile * 8 + mcol)       = v0;
                    *(float4*)(out + (size_t)(row + 8) * MPTS + tile * 8 + mcol) = v1;
                }
            }

            // ---- store next tile's pos channels into B1[nxt] (quad rows) ----
            if (dopos) {
                uint4 c8;
                c8.x = packh2(p0, p1);
                c8.y = packh2(p2, 1.0f);
                c8.z = 0u; c8.w = 0u;
                *(uint4*)(smc + nxtB + prow * 176 + 128) = c8;
            }
        }

        CP_WAIT0();            // this thread's B1[nxt] chunks complete
        BARQ(qbar);            // quad: B1[nxt]+pos published; H(t) reads done
        bufsel ^= 1;
    }
}

// ---------------------------------------------------------------------------
extern "C" void kernel_launch(void* const* d_in, const int* in_sizes, int n_in,
                              void* d_out, int out_size)
{
    const float *x = 0, *pos = 0, *sup = 0, *W1 = 0, *b1 = 0, *W2 = 0, *b2 = 0;
    const void* idx = 0;
    for (int i = 0; i < n_in; i++) {
        switch (in_sizes[i]) {
            case 4194304: x  = (const float*)d_in[i]; break;
            case 196608:  if (!pos) pos = (const float*)d_in[i];
                          else      sup = (const float*)d_in[i]; break;
            case 4288:    W1 = (const float*)d_in[i]; break;
            case 64:      b1 = (const float*)d_in[i]; break;
            case 8192:    W2 = (const float*)d_in[i]; break;
            case 128:     b2 = (const float*)d_in[i]; break;
            case 1048576: idx = d_in[i]; break;
            default: break;
        }
    }
    float* out = (float*)d_out;

    prep_all_kernel<<<NPTS / 128, 256>>>(x, W1, b1, W2, (const unsigned int*)idx);

    cudaFuncSetAttribute(pointnet_mma_kernel,
                         cudaFuncAttributeMaxDynamicSharedMemorySize, SM_TOTAL);
    pointnet_mma_kernel<<<GRID, 256, SM_TOTAL>>>(pos, sup, b2, idx, out);
}